// round 14
// baseline (speedup 1.0000x reference)
#include <cuda_runtime.h>
#include <cuda_fp16.h>
#include <math.h>
#include <stdint.h>

// Problem constants
#define NB   64
#define TT   200
#define DIN  512
#define HID  1024
#define DOUT 512
#define DELAYN 20
#define NBLK 10

// Persistent scratch (device globals — no allocation allowed)
__device__ __align__(16) __half g_xp16 [NB * TT * HID];     // x @ W_in, [B,T,H] fp16
__device__ __align__(16) __half g_fir16[TT * NB * HID];     // firing fp16, [T,B,H]
__device__ __align__(16) __half g_lat16[DELAYN * NB * HID]; // lateral contrib fp16, [s,B,H]
__device__ __align__(16) float  g_volt [NB * HID];
__device__ __align__(16) float  g_asc  [2 * NB * HID];
__device__ __align__(16) __half g_x16  [NB * TT * DIN];     // x as fp16 [B*T, IN]
__device__ __align__(16) __half g_Win16[HID * DIN];         // W_in^T  [HID, DIN]  ([N,K])
__device__ __align__(16) __half g_Wlat16[HID * HID];        // W_lat^T [HID, HID]  ([N,K])
__device__ __align__(16) __half g_Wout16[DOUT * HID];       // W_out   [DOUT, HID] ([N,K])

// ---------------------------------------------------------------------------
// mma / ldmatrix / cp.async helpers
// ---------------------------------------------------------------------------
__device__ __forceinline__ void cp16(uint32_t dst, const void* src) {
    asm volatile("cp.async.cg.shared.global [%0], [%1], 16;\n" :: "r"(dst), "l"(src));
}
template<int N>
__device__ __forceinline__ void cp_wait() {
    asm volatile("cp.async.wait_group %0;\n" :: "n"(N) : "memory");
}
__device__ __forceinline__ void ldm_x4(uint32_t* r, uint32_t addr) {
    asm volatile("ldmatrix.sync.aligned.m8n8.x4.shared.b16 {%0,%1,%2,%3}, [%4];"
        : "=r"(r[0]), "=r"(r[1]), "=r"(r[2]), "=r"(r[3]) : "r"(addr));
}
__device__ __forceinline__ void ldm_x2(uint32_t* r, uint32_t addr) {
    asm volatile("ldmatrix.sync.aligned.m8n8.x2.shared.b16 {%0,%1}, [%2];"
        : "=r"(r[0]), "=r"(r[1]) : "r"(addr));
}
__device__ __forceinline__ void mma16(float* c, const uint32_t* a, const uint32_t* b) {
    asm volatile(
        "mma.sync.aligned.m16n8k16.row.col.f32.f16.f16.f32 "
        "{%0,%1,%2,%3}, {%4,%5,%6,%7}, {%8,%9}, {%0,%1,%2,%3};\n"
        : "+f"(c[0]), "+f"(c[1]), "+f"(c[2]), "+f"(c[3])
        : "r"(a[0]), "r"(a[1]), "r"(a[2]), "r"(a[3]), "r"(b[0]), "r"(b[1]));
}

#define HSTR 40   // 40-half row pitch: ldmatrix phases cover all 32 banks

// ---------------------------------------------------------------------------
// FP16 tensor GEMM (big): 128x128 tile, BK=32, 256 threads (8 warps 2m x 4n),
// 2-stage cp.async, single __syncthreads per k-iter.
// OUT16: C is __half (pairs via __half2). REMAP: row r=t*NB+b -> C[(b*TT+t)*N].
// ---------------------------------------------------------------------------
#define BSTAGE (128 * HSTR * 2)

template<int REMAP, int BIAS, int OUT16>
__global__ __launch_bounds__(256, 2)
void gemm_f16(const __half* __restrict__ A, const __half* __restrict__ B,
              void* __restrict__ Cv, const float* __restrict__ bias,
              int M, int N, int K)
{
    __shared__ __half As[2][128 * HSTR];
    __shared__ __half Bs[2][128 * HSTR];

    const int tid  = threadIdx.x;
    const int wid  = tid >> 5;
    const int lane = tid & 31;
    const int grp  = lane >> 2;
    const int tig  = lane & 3;
    const int wm   = (wid & 1) * 64;
    const int wn   = (wid >> 1) * 32;
    const int bm   = blockIdx.y * 128;
    const int bn   = blockIdx.x * 128;

    const uint32_t sA = (uint32_t)__cvta_generic_to_shared(&As[0][0]);
    const uint32_t sB = (uint32_t)__cvta_generic_to_shared(&Bs[0][0]);

    float acc[4][4][4];
    #pragma unroll
    for (int mi = 0; mi < 4; ++mi)
        #pragma unroll
        for (int ni = 0; ni < 4; ++ni)
            #pragma unroll
            for (int j = 0; j < 4; ++j) acc[mi][ni][j] = 0.0f;

    const int nkb = K >> 5;
    const int r0 = tid >> 2, c0 = (tid & 3) * 8;
    const int r1 = (tid + 256) >> 2;

    auto load_stage = [&](int s, int kb) {
        const __half* Ag = A + (size_t)bm * K + kb * 32;
        const __half* Bg = B + (size_t)bn * K + kb * 32;
        cp16(sA + s * BSTAGE + (r0 * HSTR + c0) * 2, Ag + (size_t)r0 * K + c0);
        cp16(sA + s * BSTAGE + (r1 * HSTR + c0) * 2, Ag + (size_t)r1 * K + c0);
        cp16(sB + s * BSTAGE + (r0 * HSTR + c0) * 2, Bg + (size_t)r0 * K + c0);
        cp16(sB + s * BSTAGE + (r1 * HSTR + c0) * 2, Bg + (size_t)r1 * K + c0);
        asm volatile("cp.async.commit_group;\n" ::: "memory");
    };

    load_stage(0, 0);

    const int a_row = wm + (lane & 7) + ((lane >> 3) & 1) * 8;
    const int a_koff = (lane >> 4) * 8;
    const int b_row = wn + (lane & 7);
    const int b_koff = ((lane >> 3) & 1) * 8;

    for (int kt = 0; kt < nkb; ++kt) {
        const int s = kt & 1;
        cp_wait<0>();
        __syncthreads();
        if (kt + 1 < nkb) load_stage(s ^ 1, kt + 1);

        #pragma unroll
        for (int kc = 0; kc < 2; ++kc) {
            uint32_t af[4][4], bf[4][2];
            const int ak = kc * 16 + a_koff;
            const int bk = kc * 16 + b_koff;
            #pragma unroll
            for (int mi = 0; mi < 4; ++mi)
                ldm_x4(af[mi], sA + s * BSTAGE + ((a_row + mi * 16) * HSTR + ak) * 2);
            #pragma unroll
            for (int ni = 0; ni < 4; ++ni)
                ldm_x2(bf[ni], sB + s * BSTAGE + ((b_row + ni * 8) * HSTR + bk) * 2);
            #pragma unroll
            for (int mi = 0; mi < 4; ++mi)
                #pragma unroll
                for (int ni = 0; ni < 4; ++ni)
                    mma16(acc[mi][ni], af[mi], bf[ni]);
        }
    }
    __syncthreads();   // protect smem reuse across grid (none) / uniform exit

    #pragma unroll
    for (int mi = 0; mi < 4; ++mi) {
        const int rr0 = bm + wm + mi * 16 + grp;
        const int rr1 = rr0 + 8;
        size_t ro0, ro1;
        if (REMAP) {
            ro0 = ((size_t)(rr0 & 63) * TT + (rr0 >> 6)) * N;
            ro1 = ((size_t)(rr1 & 63) * TT + (rr1 >> 6)) * N;
        } else {
            ro0 = (size_t)rr0 * N;
            ro1 = (size_t)rr1 * N;
        }
        #pragma unroll
        for (int ni = 0; ni < 4; ++ni) {
            const int col = bn + wn + ni * 8 + tig * 2;
            if (OUT16) {
                __half* C = (__half*)Cv;
                *reinterpret_cast<__half2*>(&C[ro0 + col]) =
                    __floats2half2_rn(acc[mi][ni][0], acc[mi][ni][1]);
                *reinterpret_cast<__half2*>(&C[ro1 + col]) =
                    __floats2half2_rn(acc[mi][ni][2], acc[mi][ni][3]);
            } else {
                float* C = (float*)Cv;
                float2 v0 = make_float2(acc[mi][ni][0], acc[mi][ni][1]);
                float2 v1 = make_float2(acc[mi][ni][2], acc[mi][ni][3]);
                if (BIAS) {
                    const float bx = bias[col], by = bias[col + 1];
                    v0.x += bx; v0.y += by; v1.x += bx; v1.y += by;
                }
                *reinterpret_cast<float2*>(&C[ro0 + col]) = v0;
                *reinterpret_cast<float2*>(&C[ro1 + col]) = v1;
            }
        }
    }
}

// ---------------------------------------------------------------------------
// FP16 tensor GEMM (small, lateral): 64x64 tile, BK=32, 128 threads
// (4 warps 2x2, warp tile 32x32), 4-stage cp.async pipeline (hides L2 latency
// behind 3 compute iters), single sync per iter, fp16 output.
// Grid 16x20 = 320 CTAs.
// ---------------------------------------------------------------------------
#define SSTAGE (64 * HSTR * 2)

__global__ __launch_bounds__(128, 4)
void gemm_f16_64(const __half* __restrict__ A, const __half* __restrict__ B,
                 __half* __restrict__ C, int M, int N, int K)
{
    __shared__ __half As[4][64 * HSTR];
    __shared__ __half Bs[4][64 * HSTR];

    const int tid  = threadIdx.x;
    const int wid  = tid >> 5;
    const int lane = tid & 31;
    const int grp  = lane >> 2;
    const int tig  = lane & 3;
    const int wm   = (wid & 1) * 32;
    const int wn   = (wid >> 1) * 32;
    const int bm   = blockIdx.y * 64;
    const int bn   = blockIdx.x * 64;

    const uint32_t sA = (uint32_t)__cvta_generic_to_shared(&As[0][0]);
    const uint32_t sB = (uint32_t)__cvta_generic_to_shared(&Bs[0][0]);

    float acc[2][4][4];
    #pragma unroll
    for (int mi = 0; mi < 2; ++mi)
        #pragma unroll
        for (int ni = 0; ni < 4; ++ni)
            #pragma unroll
            for (int j = 0; j < 4; ++j) acc[mi][ni][j] = 0.0f;

    const int nkb = K >> 5;              // 32 for K=1024
    const int r0 = tid >> 2, c0 = (tid & 3) * 8;
    const int r1 = (tid + 128) >> 2;

    auto load_stage = [&](int s, int kb) {
        const __half* Ag = A + (size_t)bm * K + kb * 32;
        const __half* Bg = B + (size_t)bn * K + kb * 32;
        cp16(sA + s * SSTAGE + (r0 * HSTR + c0) * 2, Ag + (size_t)r0 * K + c0);
        cp16(sA + s * SSTAGE + (r1 * HSTR + c0) * 2, Ag + (size_t)r1 * K + c0);
        cp16(sB + s * SSTAGE + (r0 * HSTR + c0) * 2, Bg + (size_t)r0 * K + c0);
        cp16(sB + s * SSTAGE + (r1 * HSTR + c0) * 2, Bg + (size_t)r1 * K + c0);
        asm volatile("cp.async.commit_group;\n" ::: "memory");
    };

    load_stage(0, 0);
    load_stage(1, 1);
    load_stage(2, 2);

    const int a_row = wm + (lane & 7) + ((lane >> 3) & 1) * 8;
    const int a_koff = (lane >> 4) * 8;
    const int b_row = wn + (lane & 7);
    const int b_koff = ((lane >> 3) & 1) * 8;

    for (int kt = 0; kt < nkb; ++kt) {
        const int s = kt & 3;
        // pending-after-kt load count = min(2, nkb-1-kt)
        const int pend = nkb - 1 - kt;
        if (pend >= 2)      cp_wait<2>();
        else if (pend == 1) cp_wait<1>();
        else                cp_wait<0>();
        __syncthreads();
        if (kt + 3 < nkb) load_stage((kt + 3) & 3, kt + 3);

        #pragma unroll
        for (int kc = 0; kc < 2; ++kc) {
            uint32_t af[2][4], bf[4][2];
            const int ak = kc * 16 + a_koff;
            const int bk = kc * 16 + b_koff;
            #pragma unroll
            for (int mi = 0; mi < 2; ++mi)
                ldm_x4(af[mi], sA + s * SSTAGE + ((a_row + mi * 16) * HSTR + ak) * 2);
            #pragma unroll
            for (int ni = 0; ni < 4; ++ni)
                ldm_x2(bf[ni], sB + s * SSTAGE + ((b_row + ni * 8) * HSTR + bk) * 2);
            #pragma unroll
            for (int mi = 0; mi < 2; ++mi)
                #pragma unroll
                for (int ni = 0; ni < 4; ++ni)
                    mma16(acc[mi][ni], af[mi], bf[ni]);
        }
    }

    #pragma unroll
    for (int mi = 0; mi < 2; ++mi) {
        const int rr0 = bm + wm + mi * 16 + grp;
        __half* row0 = C + (size_t)rr0 * N;
        __half* row1 = C + (size_t)(rr0 + 8) * N;
        #pragma unroll
        for (int ni = 0; ni < 4; ++ni) {
            const int col = bn + wn + ni * 8 + tig * 2;
            *reinterpret_cast<__half2*>(&row0[col]) =
                __floats2half2_rn(acc[mi][ni][0], acc[mi][ni][1]);
            *reinterpret_cast<__half2*>(&row1[col]) =
                __floats2half2_rn(acc[mi][ni][2], acc[mi][ni][3]);
        }
    }
}

// ---------------------------------------------------------------------------
// fp32 -> fp16 elementwise (float4 in, 4 halves out)
// ---------------------------------------------------------------------------
__global__ void f32_to_f16(const float* __restrict__ in, __half* __restrict__ out, int n4)
{
    int i = blockIdx.x * blockDim.x + threadIdx.x;
    if (i >= n4) return;
    float4 v = reinterpret_cast<const float4*>(in)[i];
    __half2 lo = __floats2half2_rn(v.x, v.y);
    __half2 hi = __floats2half2_rn(v.z, v.w);
    uint2 o;
    o.x = *reinterpret_cast<uint32_t*>(&lo);
    o.y = *reinterpret_cast<uint32_t*>(&hi);
    reinterpret_cast<uint2*>(out)[i] = o;
}

// ---------------------------------------------------------------------------
// Transpose f32 [R,C] -> f16 [C,R]
// ---------------------------------------------------------------------------
__global__ void transpose_f16(const float* __restrict__ in, __half* __restrict__ out,
                              int R, int C)
{
    __shared__ float tile[32][33];
    const int bx = blockIdx.x * 32;
    const int by = blockIdx.y * 32;
    #pragma unroll
    for (int j = 0; j < 32; j += 8)
        tile[threadIdx.y + j][threadIdx.x] =
            in[(size_t)(by + threadIdx.y + j) * C + bx + threadIdx.x];
    __syncthreads();
    #pragma unroll
    for (int j = 0; j < 32; j += 8)
        out[(size_t)(bx + threadIdx.y + j) * R + by + threadIdx.x] =
            __float2half(tile[threadIdx.x][threadIdx.y + j]);
}

// ---------------------------------------------------------------------------
// Elementwise recurrence over DELAYN=20 steps; 4 hidden units per thread.
// xp / lat / firing all fp16 in memory; recurrence math fp32 in registers.
// ---------------------------------------------------------------------------
__global__ __launch_bounds__(64)
void step_block(int k0step, int useLat,
                const float* __restrict__ thresh,
                const float* __restrict__ tkm,
                const float* __restrict__ tak,
                const float* __restrict__ amp,
                const float* __restrict__ tar)
{
    const int idx = blockIdx.x * 64 + threadIdx.x;
    const int h = (idx & 255) * 4;
    const int b = idx >> 8;
    const int base = b * HID + h;

    float th[4], rk[4], omk[4], dk0[4], dk1[4], odk0[4], odk1[4];
    float am0[4], am1[4], rr0[4], rr1[4];
    {
        float4 t = *reinterpret_cast<const float4*>(&thresh[h]);
        th[0] = t.x; th[1] = t.y; th[2] = t.z; th[3] = t.w;
        float4 m = *reinterpret_cast<const float4*>(&tkm[h]);
        float mm[4] = {m.x, m.y, m.z, m.w};
        float4 k0v = *reinterpret_cast<const float4*>(&tak[h]);
        float4 k1v = *reinterpret_cast<const float4*>(&tak[HID + h]);
        float kk0[4] = {k0v.x, k0v.y, k0v.z, k0v.w};
        float kk1[4] = {k1v.x, k1v.y, k1v.z, k1v.w};
        float4 a0v = *reinterpret_cast<const float4*>(&amp[h]);
        float4 a1v = *reinterpret_cast<const float4*>(&amp[HID + h]);
        am0[0] = a0v.x; am0[1] = a0v.y; am0[2] = a0v.z; am0[3] = a0v.w;
        am1[0] = a1v.x; am1[1] = a1v.y; am1[2] = a1v.z; am1[3] = a1v.w;
        float4 r0v = *reinterpret_cast<const float4*>(&tar[h]);
        float4 r1v = *reinterpret_cast<const float4*>(&tar[HID + h]);
        float rv0[4] = {r0v.x, r0v.y, r0v.z, r0v.w};
        float rv1[4] = {r1v.x, r1v.y, r1v.z, r1v.w};
        #pragma unroll
        for (int j = 0; j < 4; ++j) {
            const float km = 1.0f / (1.0f + expf(-mm[j]));
            rk[j]  = 0.1f * km;
            omk[j] = 1.0f - km;
            dk0[j] = 1.0f / (1.0f + expf(-kk0[j]));
            dk1[j] = 1.0f / (1.0f + expf(-kk1[j]));
            odk0[j] = 1.0f - dk0[j];
            odk1[j] = 1.0f - dk1[j];
            rr0[j] = 1.0f - 2.0f / (1.0f + expf(-rv0[j]));
            rr1[j] = 1.0f - 2.0f / (1.0f + expf(-rv1[j]));
        }
    }

    float v[4], a0[4], a1[4], f[4];
    if (k0step == 0) {
        #pragma unroll
        for (int j = 0; j < 4; ++j) { v[j] = 0.f; a0[j] = 0.f; a1[j] = 0.f; f[j] = 0.f; }
    } else {
        float4 vv  = *reinterpret_cast<const float4*>(&g_volt[base]);
        float4 aa0 = *reinterpret_cast<const float4*>(&g_asc[base]);
        float4 aa1 = *reinterpret_cast<const float4*>(&g_asc[NB * HID + base]);
        uint2 fu = *reinterpret_cast<const uint2*>(&g_fir16[(size_t)(k0step - 1) * NB * HID + base]);
        __half2 f01 = *reinterpret_cast<__half2*>(&fu.x);
        __half2 f23 = *reinterpret_cast<__half2*>(&fu.y);
        v[0] = vv.x; v[1] = vv.y; v[2] = vv.z; v[3] = vv.w;
        a0[0] = aa0.x; a0[1] = aa0.y; a0[2] = aa0.z; a0[3] = aa0.w;
        a1[0] = aa1.x; a1[1] = aa1.y; a1[2] = aa1.z; a1[3] = aa1.w;
        f[0] = __half2float(f01.x); f[1] = __half2float(f01.y);
        f[2] = __half2float(f23.x); f[3] = __half2float(f23.y);
    }

    #pragma unroll
    for (int s = 0; s < DELAYN; ++s) {
        const int t = k0step + s;
        uint2 xu = *reinterpret_cast<const uint2*>(&g_xp16[((size_t)b * TT + t) * HID + h]);
        float2 x01 = __half22float2(*reinterpret_cast<__half2*>(&xu.x));
        float2 x23 = __half22float2(*reinterpret_cast<__half2*>(&xu.y));
        float sy[4] = {x01.x, x01.y, x23.x, x23.y};
        if (useLat) {
            uint2 lu = *reinterpret_cast<const uint2*>(&g_lat16[((size_t)s * NB + b) * HID + h]);
            float2 l01 = __half22float2(*reinterpret_cast<__half2*>(&lu.x));
            float2 l23 = __half22float2(*reinterpret_cast<__half2*>(&lu.y));
            sy[0] += l01.x; sy[1] += l01.y; sy[2] += l23.x; sy[3] += l23.y;
        }
        #pragma unroll
        for (int j = 0; j < 4; ++j) {
            a0[j] = (am0[j] + rr0[j] * a0[j]) * f[j] * dk0[j] + odk0[j] * a0[j];
            a1[j] = (am1[j] + rr1[j] * a1[j]) * f[j] * dk1[j] + odk1[j] * a1[j];
            v[j]  = rk[j] * (sy[j] + a0[j] + a1[j]) + omk[j] * v[j];
            f[j]  = __fdividef(1.0f, 1.0f + __expf(-(v[j] - th[j])));
        }
        __half2 lo = __floats2half2_rn(f[0], f[1]);
        __half2 hi = __floats2half2_rn(f[2], f[3]);
        uint2 o;
        o.x = *reinterpret_cast<uint32_t*>(&lo);
        o.y = *reinterpret_cast<uint32_t*>(&hi);
        *reinterpret_cast<uint2*>(&g_fir16[((size_t)t * NB + b) * HID + h]) = o;
    }

    *reinterpret_cast<float4*>(&g_volt[base]) = make_float4(v[0], v[1], v[2], v[3]);
    *reinterpret_cast<float4*>(&g_asc[base]) = make_float4(a0[0], a0[1], a0[2], a0[3]);
    *reinterpret_cast<float4*>(&g_asc[NB * HID + base]) = make_float4(a1[0], a1[1], a1[2], a1[3]);
}

extern "C" void kernel_launch(void* const* d_in, const int* in_sizes, int n_in,
                              void* d_out, int out_size)
{
    const float* x      = (const float*)d_in[0];
    const float* W_in   = (const float*)d_in[1];
    const float* W_lat  = (const float*)d_in[2];
    const float* thresh = (const float*)d_in[3];
    const float* tkm    = (const float*)d_in[4];
    const float* tak    = (const float*)d_in[5];
    const float* amp    = (const float*)d_in[6];
    const float* tar    = (const float*)d_in[7];
    const float* W_out  = (const float*)d_in[8];
    const float* b_out  = (const float*)d_in[9];
    float* out = (float*)d_out;

    __half *xp16, *lat16, *x16, *fir16, *win16, *wlat16, *wout16;
    cudaGetSymbolAddress((void**)&xp16,   g_xp16);
    cudaGetSymbolAddress((void**)&lat16,  g_lat16);
    cudaGetSymbolAddress((void**)&x16,    g_x16);
    cudaGetSymbolAddress((void**)&fir16,  g_fir16);
    cudaGetSymbolAddress((void**)&win16,  g_Win16);
    cudaGetSymbolAddress((void**)&wlat16, g_Wlat16);
    cudaGetSymbolAddress((void**)&wout16, g_Wout16);

    // 0) fp16 operand prep
    f32_to_f16<<<(NB * TT * DIN / 4 + 255) / 256, 256>>>(x, x16, NB * TT * DIN / 4);
    transpose_f16<<<dim3(HID / 32, DIN / 32), dim3(32, 8)>>>(W_in, win16, DIN, HID);
    transpose_f16<<<dim3(HID / 32, HID / 32), dim3(32, 8)>>>(W_lat, wlat16, HID, HID);
    f32_to_f16<<<(DOUT * HID / 4 + 255) / 256, 256>>>(W_out, wout16, DOUT * HID / 4);

    // 1) Input projection: [12800,512] @ [1024,512]^T -> g_xp16 (fp16 out)
    gemm_f16<0, 0, 1><<<dim3(HID / 128, (NB * TT) / 128), 256>>>(
        x16, win16, xp16, nullptr, NB * TT, HID, DIN);

    // 2) Ten blocks of 20 steps: lateral GEMM (4-stage, fp16 out) + recurrence
    for (int k = 0; k < NBLK; ++k) {
        if (k > 0) {
            gemm_f16_64<<<dim3(HID / 64, (DELAYN * NB) / 64), 128>>>(
                fir16 + (size_t)(k - 1) * DELAYN * NB * HID, wlat16, lat16,
                DELAYN * NB, HID, HID);
        }
        step_block<<<(NB * HID / 4) / 64, 64>>>(k * DELAYN, k > 0, thresh, tkm, tak, amp, tar);
    }

    // 3) Readout: [12800,1024] @ [512,1024]^T + bias, remapped to [B,T,OUT] (fp32 out)
    gemm_f16<1, 1, 0><<<dim3(DOUT / 128, (NB * TT) / 128), 256>>>(
        fir16, wout16, out, b_out, NB * TT, DOUT, HID);
}